// round 13
// baseline (speedup 1.0000x reference)
#include <cuda_runtime.h>

// Gray-Scott residual, Tc=2 time-chunking with EARLY EMIT to cut peak register
// pressure: residual(t=a) is stored as soon as the t=a+1 centers are available,
// channel by channel, so pua/pva/ucm/vcm die before the t=a+2 loads are issued.
// Thread tile: 2(y) x 4(x), two consecutive t. Aligned LDG.128 / LDG.64 only.
// input (20,8,3,256,256) f32 -> f_u, f_v each (20,8,1,252,252) concatenated.

#define T_DIM 20
#define B_DIM 8
#define WW 256
#define OH 252
#define OW 252
#define CS 65536
#define OPLANE (OH * OW)           // 63504
#define NOUT (T_DIM * B_DIM * OPLANE)

#define C1f (4.0f / 3.0f)
#define C2f (-1.0f / 12.0f)
#define INV_DX2 40.96f

// Exactly cols +2..+5 of one row via two aligned LDG.64.
__device__ __forceinline__ void ldn(const float* __restrict__ p, float n[4])
{
    const float2 a = *reinterpret_cast<const float2*>(p + 2);
    const float2 b = *reinterpret_cast<const float2*>(p + 4);
    n[0] = a.x; n[1] = a.y; n[2] = b.x; n[3] = b.y;
}

// Full spatial stencil for one channel at one t: scaled lap[8] + centers c[8].
__device__ __forceinline__ void spatial(const float* __restrict__ p,
                                        float lap[8], float c[8])
{
    const float4 c2a = *reinterpret_cast<const float4*>(p + 2 * WW);
    const float4 c2b = *reinterpret_cast<const float4*>(p + 2 * WW + 4);
    const float4 c3a = *reinterpret_cast<const float4*>(p + 3 * WW);
    const float4 c3b = *reinterpret_cast<const float4*>(p + 3 * WW + 4);
    float n0[4], n1[4], n4[4], n5[4];
    ldn(p,          n0);
    ldn(p + 1 * WW, n1);
    ldn(p + 4 * WW, n4);
    ldn(p + 5 * WW, n5);

    const float c2[8] = { c2a.x, c2a.y, c2a.z, c2a.w, c2b.x, c2b.y, c2b.z, c2b.w };
    const float c3[8] = { c3a.x, c3a.y, c3a.z, c3a.w, c3b.x, c3b.y, c3b.z, c3b.w };

    #pragma unroll
    for (int k = 0; k < 4; k++) {
        const float cc0 = c2[k + 2];
        const float cc1 = c3[k + 2];
        lap[k]     = (C1f * (c2[k + 1] + c2[k + 3] + n1[k] + cc1)
                    + C2f * (c2[k] + c2[k + 4] + n0[k] + n4[k])
                    - 5.0f * cc0) * INV_DX2;
        lap[k + 4] = (C1f * (c3[k + 1] + c3[k + 3] + cc0 + n4[k])
                    + C2f * (c3[k] + c3[k + 4] + n1[k] + n5[k])
                    - 5.0f * cc1) * INV_DX2;
        c[k]     = cc0;
        c[k + 4] = cc1;
    }
}

// Center-only tile (rows +2,+3, cols +2..+5).
__device__ __forceinline__ void centers(const float* __restrict__ p, float c[8])
{
    ldn(p + 2 * WW, c);
    ldn(p + 3 * WW, c + 4);
}

// Store one channel's 2x4 residual tile.
__device__ __forceinline__ void emit1(float* __restrict__ base, int yy0, int col0,
                                      const float r[8])
{
    const size_t o = (size_t)yy0 * OW + col0;
    *reinterpret_cast<float4*>(base + o)      = make_float4(r[0], r[1], r[2], r[3]);
    *reinterpret_cast<float4*>(base + o + OW) = make_float4(r[4], r[5], r[6], r[7]);
}

__global__ __launch_bounds__(128, 5) void grayscott_loss_kernel(
    const float* __restrict__ in, float* __restrict__ out)
{
    const int tx    = threadIdx.x;                 // 0..63
    const int ty    = threadIdx.y;                 // 0..1
    const int col0  = min(4 * tx, 248);            // tx==63 duplicates tx==62 (benign)
    const int yy0   = blockIdx.x * 4 + ty * 2;     // output rows yy0, yy0+1
    const int bc    = blockIdx.y;                  // 0..79, chunk-major
    const int b     = bc / 10;
    const int a     = (bc - b * 10) * 2;           // first t of chunk: 0,2,..,18

    const float Du = 0.16f, Dv = 0.08f, Ff = 0.06f, FpK = 0.122f;

    const size_t sp_off = (size_t)yy0 * WW + col0;
    const float* pa = in + ((size_t)(a * B_DIM + b) * 3 + 1) * CS + sp_off;        // u, t=a
    const float* pb = in + ((size_t)((a + 1) * B_DIM + b) * 3 + 1) * CS + sp_off;  // u, t=a+1
    float* outA  = out + (size_t)(a * B_DIM + b) * OPLANE;                          // f_u, t=a
    float* outB  = out + (size_t)((a + 1) * B_DIM + b) * OPLANE;                    // f_u, t=a+1

    // ---- backward boundary centers (t = a-1) ----
    float ucm[8], vcm[8];
    if (a > 0) {
        const float* pm = in + ((size_t)((a - 1) * B_DIM + b) * 3 + 1) * CS + sp_off;
        centers(pm, ucm);
        centers(pm + CS, vcm);
    }

    // ---- t = a: both channels -> partials ----
    float uca[8], vca[8], pua[8], pva[8];
    {
        float lapu[8];
        spatial(pa, lapu, uca);
        float lapv[8];
        spatial(pa + CS, lapv, vca);
        #pragma unroll
        for (int k = 0; k < 8; k++) {
            const float uvv = uca[k] * vca[k] * vca[k];
            pua[k] = Du * lapu[k] + Ff * (1.0f - uca[k]) - uvv;
            pva[k] = Dv * lapv[k] + uvv - FpK * vca[k];
        }
    }

    // ---- u @ a+1 stencil; early-emit res_u(a) ----
    float ucb[8], gub[8];
    {
        float lapu[8];
        spatial(pb, lapu, ucb);
        #pragma unroll
        for (int k = 0; k < 8; k++) gub[k] = Du * lapu[k] + Ff * (1.0f - ucb[k]);
    }
    if (a > 0) {
        float ru[8];
        #pragma unroll
        for (int k = 0; k < 8; k++) ru[k] = pua[k] - 10.0f * (ucb[k] - ucm[k]);
        emit1(outA, yy0, col0, ru);                 // frees pua (unless a==0 path)
    }

    // ---- v @ a+1 stencil; early-emit res_v(a) ----
    float vcb[8], pub[8], pvb[8];
    {
        float lapv[8];
        spatial(pb + CS, lapv, vcb);
        #pragma unroll
        for (int k = 0; k < 8; k++) {
            const float uvv = ucb[k] * vcb[k] * vcb[k];
            pub[k] = gub[k] - uvv;
            pvb[k] = Dv * lapv[k] + uvv - FpK * vcb[k];
        }
    }
    if (a > 0) {
        float rv[8];
        #pragma unroll
        for (int k = 0; k < 8; k++) rv[k] = pva[k] - 10.0f * (vcb[k] - vcm[k]);
        emit1(outA + NOUT, yy0, col0, rv);          // frees pva, vcm
    }

    // ---- forward boundary centers (t = a+2) ----
    float ucp[8], vcp[8];
    if (a + 2 < T_DIM) {
        const float* pp = in + ((size_t)((a + 2) * B_DIM + b) * 3 + 1) * CS + sp_off;
        centers(pp, ucp);
        centers(pp + CS, vcp);
    }

    if (a == 0) {
        // one-sided t=0: res0 = p0 + 30c0 - 40c1 + 10c2
        float ru[8], rv[8];
        #pragma unroll
        for (int k = 0; k < 8; k++) {
            ru[k] = pua[k] + 30.0f * uca[k] - 40.0f * ucb[k] + 10.0f * ucp[k];
            rv[k] = pva[k] + 30.0f * vca[k] - 40.0f * vcb[k] + 10.0f * vcp[k];
        }
        emit1(outA, yy0, col0, ru);
        emit1(outA + NOUT, yy0, col0, rv);
    }

    // ---- residual at t = a+1 ----
    {
        float ru[8], rv[8];
        if (a + 1 == T_DIM - 1) {
            // one-sided t=19: res19 = p19 - 30c19 + 40c18 - 10c17
            #pragma unroll
            for (int k = 0; k < 8; k++) {
                ru[k] = pub[k] - 30.0f * ucb[k] + 40.0f * uca[k] - 10.0f * ucm[k];
                rv[k] = pvb[k] - 30.0f * vcb[k] + 40.0f * vca[k] - 10.0f * vcm[k];
            }
        } else {
            #pragma unroll
            for (int k = 0; k < 8; k++) {
                ru[k] = pub[k] - 10.0f * (ucp[k] - uca[k]);
                rv[k] = pvb[k] - 10.0f * (vcp[k] - vca[k]);
            }
        }
        emit1(outB, yy0, col0, ru);
        emit1(outB + NOUT, yy0, col0, rv);
    }
}

extern "C" void kernel_launch(void* const* d_in, const int* in_sizes, int n_in,
                              void* d_out, int out_size)
{
    const float* in = (const float*)d_in[0];
    float* out = (float*)d_out;
    dim3 block(64, 2, 1);                        // 128 threads
    dim3 grid(OH / 4, B_DIM * (T_DIM / 2), 1);   // 63 x 80 = 5040 CTAs
    grayscott_loss_kernel<<<grid, block>>>(in, out);
}

// round 14
// speedup vs baseline: 1.4843x; 1.4843x over previous
#include <cuda_runtime.h>

// Gray-Scott residual: channel-split Tc=2.
// ty=0 warps compute f_u, ty=1 warps compute f_v for the same 2(y)x4(x) tile over
// two consecutive t. Coupling term uses other-channel CENTER loads (L1-hot, loaded
// by sibling warps) instead of smem exchange. Aligned LDG.128/LDG.64 only.
// input (20,8,3,256,256) f32 -> f_u, f_v each (20,8,1,252,252) concatenated.

#define T_DIM 20
#define B_DIM 8
#define WW 256
#define OH 252
#define OW 252
#define CS 65536
#define OPLANE (OH * OW)           // 63504
#define NOUT (T_DIM * B_DIM * OPLANE)

#define C1f (4.0f / 3.0f)
#define C2f (-1.0f / 12.0f)
#define INV_DX2 40.96f

// Exactly cols +2..+5 of one row via two aligned LDG.64.
__device__ __forceinline__ void ldn(const float* __restrict__ p, float n[4])
{
    const float2 a = *reinterpret_cast<const float2*>(p + 2);
    const float2 b = *reinterpret_cast<const float2*>(p + 4);
    n[0] = a.x; n[1] = a.y; n[2] = b.x; n[3] = b.y;
}

// Full spatial stencil at one t: scaled lap[8] + centers c[8] (2 rows x 4 cols).
__device__ __forceinline__ void spatial(const float* __restrict__ p,
                                        float lap[8], float c[8])
{
    const float4 c2a = *reinterpret_cast<const float4*>(p + 2 * WW);
    const float4 c2b = *reinterpret_cast<const float4*>(p + 2 * WW + 4);
    const float4 c3a = *reinterpret_cast<const float4*>(p + 3 * WW);
    const float4 c3b = *reinterpret_cast<const float4*>(p + 3 * WW + 4);
    float n0[4], n1[4], n4[4], n5[4];
    ldn(p,          n0);
    ldn(p + 1 * WW, n1);
    ldn(p + 4 * WW, n4);
    ldn(p + 5 * WW, n5);

    const float c2[8] = { c2a.x, c2a.y, c2a.z, c2a.w, c2b.x, c2b.y, c2b.z, c2b.w };
    const float c3[8] = { c3a.x, c3a.y, c3a.z, c3a.w, c3b.x, c3b.y, c3b.z, c3b.w };

    #pragma unroll
    for (int k = 0; k < 4; k++) {
        const float cc0 = c2[k + 2];
        const float cc1 = c3[k + 2];
        lap[k]     = (C1f * (c2[k + 1] + c2[k + 3] + n1[k] + cc1)
                    + C2f * (c2[k] + c2[k + 4] + n0[k] + n4[k])
                    - 5.0f * cc0) * INV_DX2;
        lap[k + 4] = (C1f * (c3[k + 1] + c3[k + 3] + cc0 + n4[k])
                    + C2f * (c3[k] + c3[k + 4] + n1[k] + n5[k])
                    - 5.0f * cc1) * INV_DX2;
        c[k]     = cc0;
        c[k + 4] = cc1;
    }
}

// Center-only tile (rows +2,+3, cols +2..+5).
__device__ __forceinline__ void centers(const float* __restrict__ p, float c[8])
{
    ldn(p + 2 * WW, c);
    ldn(p + 3 * WW, c + 4);
}

// Store one channel's 2x4 residual tile.
__device__ __forceinline__ void emit1(float* __restrict__ base, int yy0, int col0,
                                      const float r[8])
{
    const size_t o = (size_t)yy0 * OW + col0;
    *reinterpret_cast<float4*>(base + o)      = make_float4(r[0], r[1], r[2], r[3]);
    *reinterpret_cast<float4*>(base + o + OW) = make_float4(r[4], r[5], r[6], r[7]);
}

__global__ __launch_bounds__(128) void grayscott_loss_kernel(
    const float* __restrict__ in, float* __restrict__ out)
{
    const int tx   = threadIdx.x;                 // 0..63
    const int ch   = threadIdx.y;                 // 0 = u (f_u), 1 = v (f_v); warp-uniform
    const int col0 = min(4 * tx, 248);            // tx==63 duplicates tx==62 (benign)
    const int yy0  = blockIdx.x * 2;              // output rows yy0, yy0+1
    const int bc   = blockIdx.y;                  // 0..79
    const int b    = bc & 7;
    const int a    = (bc >> 3) * 2;               // first t of chunk: 0,2,..,18

    const size_t sp_off = (size_t)yy0 * WW + col0;

    // plane(t) for my channel / other channel
    const size_t tbase_a  = ((size_t)(a * B_DIM + b) * 3 + 1) * CS;
    const size_t tbase_b  = ((size_t)((a + 1) * B_DIM + b) * 3 + 1) * CS;
    const int    chOff    = ch * CS;              // my channel offset within the 3-ch block
    const int    otherOff = (1 - ch) * CS;

    const float* pA = in + tbase_a + chOff + sp_off;      // my channel, t=a
    const float* pB = in + tbase_b + chOff + sp_off;      // my channel, t=a+1

    // ---- own spatial stencils ----
    float lapA[8], cA[8], lapB[8], cB[8];
    spatial(pA, lapA, cA);
    spatial(pB, lapB, cB);

    // ---- other-channel centers (L1-hot: loaded as centers by sibling warps) ----
    float oA[8], oB[8];
    centers(in + tbase_a + otherOff + sp_off, oA);
    centers(in + tbase_b + otherOff + sp_off, oB);

    // ---- own time-boundary centers ----
    float cm[8], cp[8];
    if (a > 0)
        centers(in + ((size_t)((a - 1) * B_DIM + b) * 3 + 1) * CS + chOff + sp_off, cm);
    if (a + 2 < T_DIM)
        centers(in + ((size_t)((a + 2) * B_DIM + b) * 3 + 1) * CS + chOff + sp_off, cp);

    // ---- reaction + diffusion partials ----
    const float D   = ch ? 0.08f : 0.16f;
    const float Ff  = 0.06f, FpK = 0.122f;

    float pAr[8], pBr[8];
    #pragma unroll
    for (int k = 0; k < 8; k++) {
        // uvv = u * v^2 ; for ch==0: cA=u, oA=v ; for ch==1: cA=v, oA=u
        const float uvvA = ch ? (oA[k] * cA[k] * cA[k]) : (cA[k] * oA[k] * oA[k]);
        const float uvvB = ch ? (oB[k] * cB[k] * cB[k]) : (cB[k] * oB[k] * oB[k]);
        const float reactA = ch ? (uvvA - FpK * cA[k]) : (Ff * (1.0f - cA[k]) - uvvA);
        const float reactB = ch ? (uvvB - FpK * cB[k]) : (Ff * (1.0f - cB[k]) - uvvB);
        pAr[k] = D * lapA[k] + reactA;
        pBr[k] = D * lapB[k] + reactB;
    }

    float* outMy = out + (size_t)ch * NOUT;

    // ---- residual at t = a ----
    {
        float r[8];
        if (a == 0) {
            // one-sided: res0 = p0 + 30c0 - 40c1 + 10c2
            #pragma unroll
            for (int k = 0; k < 8; k++)
                r[k] = pAr[k] + 30.0f * cA[k] - 40.0f * cB[k] + 10.0f * cp[k];
        } else {
            #pragma unroll
            for (int k = 0; k < 8; k++)
                r[k] = pAr[k] - 10.0f * (cB[k] - cm[k]);
        }
        emit1(outMy + (size_t)(a * B_DIM + b) * OPLANE, yy0, col0, r);
    }

    // ---- residual at t = a+1 ----
    {
        float r[8];
        if (a + 1 == T_DIM - 1) {
            // one-sided: res19 = p19 - 30c19 + 40c18 - 10c17
            #pragma unroll
            for (int k = 0; k < 8; k++)
                r[k] = pBr[k] - 30.0f * cB[k] + 40.0f * cA[k] - 10.0f * cm[k];
        } else {
            #pragma unroll
            for (int k = 0; k < 8; k++)
                r[k] = pBr[k] - 10.0f * (cp[k] - cA[k]);
        }
        emit1(outMy + (size_t)((a + 1) * B_DIM + b) * OPLANE, yy0, col0, r);
    }
}

extern "C" void kernel_launch(void* const* d_in, const int* in_sizes, int n_in,
                              void* d_out, int out_size)
{
    const float* in = (const float*)d_in[0];
    float* out = (float*)d_out;
    dim3 block(64, 2, 1);                        // 128 threads: ty=0 -> f_u, ty=1 -> f_v
    dim3 grid(OH / 2, B_DIM * (T_DIM / 2), 1);   // 126 x 80 = 10080 CTAs
    grayscott_loss_kernel<<<grid, block>>>(in, out);
}